// round 2
// baseline (speedup 1.0000x reference)
#include <cuda_runtime.h>
#include <cuda_bf16.h>
#include <cstdint>

// ---------------- problem geometry ----------------
#define T_TOK   4096        // B*SQ tokens
#define D_MODEL 4096
#define H_HEADS 32
#define DHEAD   128
#define B_SEQ   4
#define SQ      1024
#define HIST    1024
#define SKV     2048
#define NBLK    32
#define BS_PAGE 64
#define ATT_SCALE  0.08838834764831845f   // 1/sqrt(128)
#define INV_LN1024 0.14426950408889634f   // 1/ln(1024)

// ---------------- scratch (device globals: no allocations allowed) ----------
__device__ float g_qkv[50331648];   // [T, 3*D]  192 MB
__device__ float g_k  [33554432];   // [B,H,SKV,DH] 128 MB
__device__ float g_v  [33554432];   // [B,H,SKV,DH] 128 MB
__device__ float g_attn[16777216];  // [T, D]     64 MB

// =====================================================================
// SGEMM: C[M,N] = A[M,K] @ B[K,N] (+bias).  128x128x8 tile, 8x8 micro.
// =====================================================================
__global__ __launch_bounds__(256) void sgemm_kernel(
    const float* __restrict__ A, const float* __restrict__ Bm,
    const float* __restrict__ bias, float* __restrict__ C,
    int M, int N, int K)
{
    __shared__ float As[8][128];
    __shared__ float Bs[8][128];
    const int tid  = threadIdx.x;
    const int brow = blockIdx.y, bcol = blockIdx.x;
    const float* Ab = A + (size_t)brow * 128 * K;
    const float* Bb = Bm + (size_t)bcol * 128;

    const int a_row = tid >> 1,  a_col = (tid & 1) << 2;
    const int b_row = tid >> 5,  b_col = (tid & 31) << 2;
    const int ty = tid >> 4, tx = tid & 15;

    float acc[8][8];
    #pragma unroll
    for (int i = 0; i < 8; i++)
        #pragma unroll
        for (int j = 0; j < 8; j++) acc[i][j] = 0.f;

    float4 av = *(const float4*)(Ab + (size_t)a_row * K + a_col);
    float4 bv = *(const float4*)(Bb + (size_t)b_row * N + b_col);

    for (int kt = 0; kt < K; kt += 8) {
        As[a_col + 0][a_row] = av.x;
        As[a_col + 1][a_row] = av.y;
        As[a_col + 2][a_row] = av.z;
        As[a_col + 3][a_row] = av.w;
        *(float4*)&Bs[b_row][b_col] = bv;
        __syncthreads();

        float4 av_n = av, bv_n = bv;
        if (kt + 8 < K) {
            av_n = *(const float4*)(Ab + (size_t)a_row * K + (kt + 8) + a_col);
            bv_n = *(const float4*)(Bb + (size_t)(kt + 8 + b_row) * N + b_col);
        }

        #pragma unroll
        for (int k = 0; k < 8; k++) {
            float af[8], bf[8];
            *(float4*)(af)     = *(float4*)&As[k][ty * 8];
            *(float4*)(af + 4) = *(float4*)&As[k][ty * 8 + 4];
            *(float4*)(bf)     = *(float4*)&Bs[k][tx * 8];
            *(float4*)(bf + 4) = *(float4*)&Bs[k][tx * 8 + 4];
            #pragma unroll
            for (int i = 0; i < 8; i++)
                #pragma unroll
                for (int j = 0; j < 8; j++)
                    acc[i][j] += af[i] * bf[j];
        }
        __syncthreads();
        av = av_n; bv = bv_n;
    }

    const size_t row0 = (size_t)brow * 128 + ty * 8;
    const int    col0 = bcol * 128 + tx * 8;
    float bload[8];
    #pragma unroll
    for (int j = 0; j < 8; j++) bload[j] = bias ? bias[col0 + j] : 0.f;
    #pragma unroll
    for (int i = 0; i < 8; i++) {
        float4 r0, r1;
        r0.x = acc[i][0] + bload[0]; r0.y = acc[i][1] + bload[1];
        r0.z = acc[i][2] + bload[2]; r0.w = acc[i][3] + bload[3];
        r1.x = acc[i][4] + bload[4]; r1.y = acc[i][5] + bload[5];
        r1.z = acc[i][6] + bload[6]; r1.w = acc[i][7] + bload[7];
        *(float4*)&C[(row0 + i) * N + col0]     = r0;
        *(float4*)&C[(row0 + i) * N + col0 + 4] = r1;
    }
}

// =====================================================================
// RoPE + logn scale applied to Q in place inside g_qkv.
// grid (T, H), block 64 (thread d handles pair d, d+64).
// pos is deterministic for this problem: pos = HIST + (t % SQ).
// =====================================================================
__global__ void rope_q_kernel(float* __restrict__ qkv,
                              const float* __restrict__ cosT,
                              const float* __restrict__ sinT)
{
    const int t = blockIdx.x, h = blockIdx.y, d = threadIdx.x;
    const int pos = HIST + (t & (SQ - 1));
    // pos+1 ranges 1025..2048 > 1024 always -> logn active
    const float logn = logf((float)(pos + 1)) * INV_LN1024;
    float* q = qkv + (size_t)t * (3 * D_MODEL) + h * DHEAD;
    const float c1 = cosT[(size_t)pos * DHEAD + d];
    const float c2 = cosT[(size_t)pos * DHEAD + d + 64];
    const float s1 = sinT[(size_t)pos * DHEAD + d];
    const float s2 = sinT[(size_t)pos * DHEAD + d + 64];
    const float q1 = q[d], q2 = q[d + 64];
    q[d]      = (q1 * c1 - q2 * s1) * logn;
    q[d + 64] = (q2 * c2 + q1 * s2) * logn;
}

// =====================================================================
// Build contiguous K/V [B,H,SKV,DH]: history gathered from paged cache,
// new tokens RoPE'd from g_qkv.  grid (SKV, B), block 128.
// New-token absolute position == s.
// =====================================================================
__global__ void build_kv_kernel(const float* __restrict__ qkv,
                                const float* __restrict__ kcache,
                                const float* __restrict__ vcache,
                                const int* __restrict__ blockOff,
                                const float* __restrict__ cosT,
                                const float* __restrict__ sinT,
                                float* __restrict__ Kout,
                                float* __restrict__ Vout)
{
    const int s = blockIdx.x, b = blockIdx.y, d = threadIdx.x;
    if (s < HIST) {
        const int blk = blockOff[b * NBLK + (s >> 6)];
        const size_t src = ((size_t)(blk * BS_PAGE + (s & 63))) * H_HEADS * DHEAD;
        for (int h = 0; h < H_HEADS; h++) {
            const size_t dst = (((size_t)(b * H_HEADS + h)) * SKV + s) * DHEAD + d;
            Kout[dst] = kcache[src + h * DHEAD + d];
            Vout[dst] = vcache[src + h * DHEAD + d];
        }
    } else {
        const int t = b * SQ + (s - HIST);
        const int pos = s;                       // absolute position of token t
        const float c  = cosT[(size_t)pos * DHEAD + d];
        const float sn = sinT[(size_t)pos * DHEAD + d];
        const float* kp = qkv + (size_t)t * (3 * D_MODEL) + D_MODEL;
        const float* vp = kp + D_MODEL;
        for (int h = 0; h < H_HEADS; h++) {
            const float k1 = kp[h * DHEAD + d];
            const float rot = (d < 64) ? -kp[h * DHEAD + d + 64]
                                       :  kp[h * DHEAD + d - 64];
            const size_t dst = (((size_t)(b * H_HEADS + h)) * SKV + s) * DHEAD + d;
            Kout[dst] = k1 * c + rot * sn;
            Vout[dst] = vp[h * DHEAD + d];
        }
    }
}

// =====================================================================
// Flash attention, fp32.  One block per (b*h, q-tile of 64).
// 256 threads. smem: Qs[64][128], Ks[64][132], Vs[64][128], Ps[64][65].
// =====================================================================
#define FL_SMEM_FLOATS (64*128 + 64*132 + 64*128 + 64*65 + 3*64)
#define FL_SMEM_BYTES  (FL_SMEM_FLOATS * 4)

__global__ __launch_bounds__(256) void flash_kernel(
    const float* __restrict__ Qg,   // g_qkv (q section, RoPE'd)
    const float* __restrict__ Kg,   // g_k
    const float* __restrict__ Vg,   // g_v
    float* __restrict__ Og)         // g_attn [T,D]
{
    const int bh = blockIdx.x;
    const int b = bh >> 5, h = bh & 31;
    const int q0 = blockIdx.y * 64;
    extern __shared__ float sm[];
    float* Qs  = sm;                 // stride 128
    float* Ks  = Qs + 64 * 128;      // stride 132
    float* Vs  = Ks + 64 * 132;      // stride 128
    float* Ps  = Vs + 64 * 128;      // stride 65
    float* m_s = Ps + 64 * 65;
    float* l_s = m_s + 64;
    float* c_s = l_s + 64;

    const int tid = threadIdx.x;
    const int ty = tid >> 4, tx = tid & 15;       // S micro-tile owner
    const int rg = tid >> 5, lane = tid & 31;     // O micro-tile owner

    // load Q tile
    for (int idx = tid; idx < 64 * 32; idx += 256) {
        const int r = idx >> 5, d4 = (idx & 31) << 2;
        const int t = b * SQ + q0 + r;
        *(float4*)&Qs[r * 128 + d4] =
            *(const float4*)&Qg[(size_t)t * (3 * D_MODEL) + h * DHEAD + d4];
    }
    if (tid < 64) { m_s[tid] = -1e30f; l_s[tid] = 0.f; }

    float o[8][4];
    #pragma unroll
    for (int i = 0; i < 8; i++)
        { o[i][0]=0.f; o[i][1]=0.f; o[i][2]=0.f; o[i][3]=0.f; }

    const float* Kbh = Kg + (size_t)bh * SKV * DHEAD;
    const float* Vbh = Vg + (size_t)bh * SKV * DHEAD;
    const int ntiles = (HIST + q0) / 64 + 1;
    __syncthreads();

    for (int kt = 0; kt < ntiles; kt++) {
        const int s0 = kt * 64;
        // load K/V tiles
        for (int idx = tid; idx < 64 * 32; idx += 256) {
            const int s = idx >> 5, d4 = (idx & 31) << 2;
            *(float4*)&Ks[s * 132 + d4] =
                *(const float4*)&Kbh[(size_t)(s0 + s) * DHEAD + d4];
            *(float4*)&Vs[s * 128 + d4] =
                *(const float4*)&Vbh[(size_t)(s0 + s) * DHEAD + d4];
        }
        __syncthreads();

        // S = Q @ K^T  (thread owns rows ty*4+i, cols tx+16*j)
        float acc[4][4];
        #pragma unroll
        for (int i = 0; i < 4; i++)
            #pragma unroll
            for (int j = 0; j < 4; j++) acc[i][j] = 0.f;

        #pragma unroll 4
        for (int kk = 0; kk < 128; kk += 4) {
            float4 qf[4], kf[4];
            #pragma unroll
            for (int i = 0; i < 4; i++)
                qf[i] = *(float4*)&Qs[(ty * 4 + i) * 128 + kk];
            #pragma unroll
            for (int j = 0; j < 4; j++)
                kf[j] = *(float4*)&Ks[(tx + 16 * j) * 132 + kk];
            #pragma unroll
            for (int i = 0; i < 4; i++)
                #pragma unroll
                for (int j = 0; j < 4; j++) {
                    acc[i][j] += qf[i].x * kf[j].x;
                    acc[i][j] += qf[i].y * kf[j].y;
                    acc[i][j] += qf[i].z * kf[j].z;
                    acc[i][j] += qf[i].w * kf[j].w;
                }
        }

        // scale + causal mask + write to Ps
        #pragma unroll
        for (int i = 0; i < 4; i++) {
            const int qpos = HIST + q0 + ty * 4 + i;
            #pragma unroll
            for (int j = 0; j < 4; j++) {
                const int s = s0 + tx + 16 * j;
                float v = acc[i][j] * ATT_SCALE;
                if (s > qpos) v = -1e30f;
                Ps[(ty * 4 + i) * 65 + tx + 16 * j] = v;
            }
        }
        __syncthreads();

        // online softmax: 4 threads per row
        {
            const int row = tid >> 2, qq = tid & 3;
            float* prow = Ps + row * 65 + qq * 16;
            float mx = -1e30f;
            #pragma unroll
            for (int k = 0; k < 16; k++) mx = fmaxf(mx, prow[k]);
            mx = fmaxf(mx, __shfl_xor_sync(0xffffffffu, mx, 1));
            mx = fmaxf(mx, __shfl_xor_sync(0xffffffffu, mx, 2));
            const float m_old = m_s[row];
            const float m_new = fmaxf(m_old, mx);
            float ssum = 0.f;
            #pragma unroll
            for (int k = 0; k < 16; k++) {
                const float p = __expf(prow[k] - m_new);
                prow[k] = p; ssum += p;
            }
            ssum += __shfl_xor_sync(0xffffffffu, ssum, 1);
            ssum += __shfl_xor_sync(0xffffffffu, ssum, 2);
            if (qq == 0) {
                const float corr = __expf(m_old - m_new);
                l_s[row] = l_s[row] * corr + ssum;
                m_s[row] = m_new;
                c_s[row] = corr;
            }
        }
        __syncthreads();

        // O = O*corr + P @ V  (thread owns rows rg*8+i, cols lane*4..+3)
        #pragma unroll
        for (int i = 0; i < 8; i++) {
            const float c = c_s[rg * 8 + i];
            o[i][0] *= c; o[i][1] *= c; o[i][2] *= c; o[i][3] *= c;
        }
        #pragma unroll 4
        for (int kv = 0; kv < 64; kv++) {
            const float4 v = *(float4*)&Vs[kv * 128 + lane * 4];
            #pragma unroll
            for (int i = 0; i < 8; i++) {
                const float p = Ps[(rg * 8 + i) * 65 + kv];
                o[i][0] += p * v.x; o[i][1] += p * v.y;
                o[i][2] += p * v.z; o[i][3] += p * v.w;
            }
        }
        __syncthreads();
    }

    // finalize
    #pragma unroll
    for (int i = 0; i < 8; i++) {
        const int r = rg * 8 + i;
        const float inv = 1.f / l_s[r];
        const int t = b * SQ + q0 + r;
        float4 res;
        res.x = o[i][0] * inv; res.y = o[i][1] * inv;
        res.z = o[i][2] * inv; res.w = o[i][3] * inv;
        *(float4*)&Og[(size_t)t * D_MODEL + h * DHEAD + lane * 4] = res;
    }
}

// =====================================================================
// launch
// =====================================================================
extern "C" void kernel_launch(void* const* d_in, const int* in_sizes, int n_in,
                              void* d_out, int out_size)
{
    const float*     hidden  = (const float*)d_in[0];
    const float*     w_qkv   = (const float*)d_in[1];
    const float*     b_qkv   = (const float*)d_in[2];
    const float*     w_proj  = (const float*)d_in[3];
    const float*     cosT    = (const float*)d_in[4];
    const float*     sinT    = (const float*)d_in[5];
    const float*     kcache  = (const float*)d_in[6];
    const float*     vcache  = (const float*)d_in[7];
    const int*       blkOff  = (const int*)d_in[8];
    float* out = (float*)d_out;

    float *qkv_p, *k_p, *v_p, *attn_p;
    cudaGetSymbolAddress((void**)&qkv_p,  g_qkv);
    cudaGetSymbolAddress((void**)&k_p,    g_k);
    cudaGetSymbolAddress((void**)&v_p,    g_v);
    cudaGetSymbolAddress((void**)&attn_p, g_attn);

    cudaFuncSetAttribute(flash_kernel,
                         cudaFuncAttributeMaxDynamicSharedMemorySize,
                         FL_SMEM_BYTES);

    // 1) QKV projection: [T, 3D] = hidden[T,D] @ w_qkv[D,3D] + b
    sgemm_kernel<<<dim3(3 * D_MODEL / 128, T_TOK / 128), 256>>>(
        hidden, w_qkv, b_qkv, qkv_p, T_TOK, 3 * D_MODEL, D_MODEL);

    // 2) RoPE + logn on Q (in place)
    rope_q_kernel<<<dim3(T_TOK, H_HEADS), 64>>>(qkv_p, cosT, sinT);

    // 3) build contiguous K/V (cache gather + RoPE on new K)
    build_kv_kernel<<<dim3(SKV, B_SEQ), 128>>>(
        qkv_p, kcache, vcache, blkOff, cosT, sinT, k_p, v_p);

    // 4) causal flash attention
    flash_kernel<<<dim3(B_SEQ * H_HEADS, SQ / 64), 256, FL_SMEM_BYTES>>>(
        qkv_p, k_p, v_p, attn_p);

    // 5) output projection: out[T,D] = attn[T,D] @ w_proj[D,D]
    sgemm_kernel<<<dim3(D_MODEL / 128, T_TOK / 128), 256>>>(
        attn_p, w_proj, nullptr, out, T_TOK, D_MODEL, D_MODEL);
}

// round 3
// speedup vs baseline: 2.0475x; 2.0475x over previous
#include <cuda_runtime.h>
#include <cuda_bf16.h>
#include <cstdint>

// ---------------- problem geometry ----------------
#define T_TOK   4096        // B*SQ tokens
#define D_MODEL 4096
#define H_HEADS 32
#define DHEAD   128
#define B_SEQ   4
#define SQ      1024
#define HIST    1024
#define SKV     2048
#define NBLK    32
#define BS_PAGE 64
#define ATT_SCALE  0.08838834764831845f   // 1/sqrt(128)
#define INV_LN1024 0.14426950408889634f   // 1/ln(1024)

// ---------------- scratch (device globals: no allocations allowed) ----------
__device__ float g_qkv[50331648];   // [T, 3*D]  192 MB
__device__ float g_k  [33554432];   // [B,H,SKV,DH] 128 MB
__device__ float g_v  [33554432];   // [B,H,SKV,DH] 128 MB
__device__ float g_attn[16777216];  // [T, D]     64 MB

// =====================================================================
// TF32 tensor-core GEMM: C[M,N] = A[M,K] @ B[K,N] (+bias)
// Block tile 128x128, K-tile 32. 8 warps; warp tile 64x32 via
// mma.sync.m16n8k8.tf32 (4 m-tiles x 4 n-tiles).
// =====================================================================
__device__ __forceinline__ uint32_t f2tf32(float f) {
    uint32_t u;
    asm("cvt.rna.tf32.f32 %0, %1;" : "=r"(u) : "f"(f));
    return u;
}

__global__ __launch_bounds__(256, 2) void tf32_gemm_kernel(
    const float* __restrict__ A, const float* __restrict__ Bm,
    const float* __restrict__ bias, float* __restrict__ C,
    int M, int N, int K)
{
    __shared__ uint32_t As[128][36];   // [m][k], stride 36 -> conflict-free frags
    __shared__ uint32_t Bs[32][136];   // [k][n], stride 136 -> conflict-free frags

    const int tid  = threadIdx.x;
    const int brow = blockIdx.y, bcol = blockIdx.x;
    const int warp = tid >> 5, lane = tid & 31;
    const int wr = warp >> 2, wc = warp & 3;      // warp grid 2x4
    const int gp = lane >> 2, q = lane & 3;

    float acc[4][4][4];
    #pragma unroll
    for (int mt = 0; mt < 4; mt++)
        #pragma unroll
        for (int nt = 0; nt < 4; nt++)
            #pragma unroll
            for (int r = 0; r < 4; r++) acc[mt][nt][r] = 0.f;

    const float* Ab = A + (size_t)(brow * 128) * K;
    const float* Bb = Bm + (size_t)bcol * 128;

    for (int kt = 0; kt < K; kt += 32) {
        // ---- global load (4 float4 of A + 4 float4 of B per thread) ----
        float4 av[4], bv[4];
        #pragma unroll
        for (int i = 0; i < 4; i++) {
            const int u = tid + 256 * i;
            av[i] = *(const float4*)(Ab + (size_t)(u >> 3) * K + kt + ((u & 7) << 2));
            bv[i] = *(const float4*)(Bb + (size_t)(kt + (u >> 5)) * N + ((u & 31) << 2));
        }
        // ---- convert to tf32 + store to smem ----
        #pragma unroll
        for (int i = 0; i < 4; i++) {
            const int u = tid + 256 * i;
            uint4 ta, tb;
            ta.x = f2tf32(av[i].x); ta.y = f2tf32(av[i].y);
            ta.z = f2tf32(av[i].z); ta.w = f2tf32(av[i].w);
            tb.x = f2tf32(bv[i].x); tb.y = f2tf32(bv[i].y);
            tb.z = f2tf32(bv[i].z); tb.w = f2tf32(bv[i].w);
            *(uint4*)&As[u >> 3][(u & 7) << 2]  = ta;
            *(uint4*)&Bs[u >> 5][(u & 31) << 2] = tb;
        }
        __syncthreads();

        // ---- mma phase: 4 kk-steps of 8 ----
        #pragma unroll
        for (int kk = 0; kk < 32; kk += 8) {
            uint32_t af[4][4], bf[4][2];
            #pragma unroll
            for (int mt = 0; mt < 4; mt++) {
                const int r = wr * 64 + mt * 16 + gp;
                af[mt][0] = As[r][kk + q];
                af[mt][1] = As[r + 8][kk + q];
                af[mt][2] = As[r][kk + q + 4];
                af[mt][3] = As[r + 8][kk + q + 4];
            }
            #pragma unroll
            for (int nt = 0; nt < 4; nt++) {
                const int c = wc * 32 + nt * 8 + gp;
                bf[nt][0] = Bs[kk + q][c];
                bf[nt][1] = Bs[kk + q + 4][c];
            }
            #pragma unroll
            for (int mt = 0; mt < 4; mt++)
                #pragma unroll
                for (int nt = 0; nt < 4; nt++) {
                    asm volatile(
                        "mma.sync.aligned.m16n8k8.row.col.f32.tf32.tf32.f32 "
                        "{%0,%1,%2,%3}, {%4,%5,%6,%7}, {%8,%9}, {%0,%1,%2,%3};"
                        : "+f"(acc[mt][nt][0]), "+f"(acc[mt][nt][1]),
                          "+f"(acc[mt][nt][2]), "+f"(acc[mt][nt][3])
                        : "r"(af[mt][0]), "r"(af[mt][1]),
                          "r"(af[mt][2]), "r"(af[mt][3]),
                          "r"(bf[nt][0]), "r"(bf[nt][1]));
                }
        }
        __syncthreads();
    }

    // ---- epilogue ----
    #pragma unroll
    for (int mt = 0; mt < 4; mt++) {
        const int r0 = brow * 128 + wr * 64 + mt * 16 + gp;
        #pragma unroll
        for (int nt = 0; nt < 4; nt++) {
            const int c0 = bcol * 128 + wc * 32 + nt * 8 + 2 * q;
            float bb0 = 0.f, bb1 = 0.f;
            if (bias) { bb0 = bias[c0]; bb1 = bias[c0 + 1]; }
            float2 v0, v1;
            v0.x = acc[mt][nt][0] + bb0; v0.y = acc[mt][nt][1] + bb1;
            v1.x = acc[mt][nt][2] + bb0; v1.y = acc[mt][nt][3] + bb1;
            *(float2*)&C[(size_t)r0 * N + c0]       = v0;
            *(float2*)&C[(size_t)(r0 + 8) * N + c0] = v1;
        }
    }
}

// =====================================================================
// RoPE + logn scale applied to Q in place inside g_qkv.
// pos = HIST + (t % SQ) deterministically for this problem.
// =====================================================================
__global__ void rope_q_kernel(float* __restrict__ qkv,
                              const float* __restrict__ cosT,
                              const float* __restrict__ sinT)
{
    const int t = blockIdx.x, h = blockIdx.y, d = threadIdx.x;
    const int pos = HIST + (t & (SQ - 1));
    const float logn = logf((float)(pos + 1)) * INV_LN1024;
    float* qp = qkv + (size_t)t * (3 * D_MODEL) + h * DHEAD;
    const float c1 = cosT[(size_t)pos * DHEAD + d];
    const float c2 = cosT[(size_t)pos * DHEAD + d + 64];
    const float s1 = sinT[(size_t)pos * DHEAD + d];
    const float s2 = sinT[(size_t)pos * DHEAD + d + 64];
    const float q1 = qp[d], q2 = qp[d + 64];
    qp[d]      = (q1 * c1 - q2 * s1) * logn;
    qp[d + 64] = (q2 * c2 + q1 * s2) * logn;
}

// =====================================================================
// Build contiguous K/V [B,H,SKV,DH]: history gathered from paged cache,
// new tokens RoPE'd from g_qkv.  grid (SKV, B), block 128.
// =====================================================================
__global__ void build_kv_kernel(const float* __restrict__ qkv,
                                const float* __restrict__ kcache,
                                const float* __restrict__ vcache,
                                const int* __restrict__ blockOff,
                                const float* __restrict__ cosT,
                                const float* __restrict__ sinT,
                                float* __restrict__ Kout,
                                float* __restrict__ Vout)
{
    const int s = blockIdx.x, b = blockIdx.y, d = threadIdx.x;
    if (s < HIST) {
        const int blk = blockOff[b * NBLK + (s >> 6)];
        const size_t src = ((size_t)(blk * BS_PAGE + (s & 63))) * H_HEADS * DHEAD;
        for (int h = 0; h < H_HEADS; h++) {
            const size_t dst = (((size_t)(b * H_HEADS + h)) * SKV + s) * DHEAD + d;
            Kout[dst] = kcache[src + h * DHEAD + d];
            Vout[dst] = vcache[src + h * DHEAD + d];
        }
    } else {
        const int t = b * SQ + (s - HIST);
        const int pos = s;
        const float c  = cosT[(size_t)pos * DHEAD + d];
        const float sn = sinT[(size_t)pos * DHEAD + d];
        const float* kp = qkv + (size_t)t * (3 * D_MODEL) + D_MODEL;
        const float* vp = kp + D_MODEL;
        for (int h = 0; h < H_HEADS; h++) {
            const float k1 = kp[h * DHEAD + d];
            const float rot = (d < 64) ? -kp[h * DHEAD + d + 64]
                                       :  kp[h * DHEAD + d - 64];
            const size_t dst = (((size_t)(b * H_HEADS + h)) * SKV + s) * DHEAD + d;
            Kout[dst] = k1 * c + rot * sn;
            Vout[dst] = vp[h * DHEAD + d];
        }
    }
}

// =====================================================================
// Flash attention, fp32.  One block per (b*h, q-tile of 64).
// =====================================================================
#define FL_SMEM_FLOATS (64*128 + 64*132 + 64*128 + 64*65 + 3*64)
#define FL_SMEM_BYTES  (FL_SMEM_FLOATS * 4)

__global__ __launch_bounds__(256) void flash_kernel(
    const float* __restrict__ Qg,
    const float* __restrict__ Kg,
    const float* __restrict__ Vg,
    float* __restrict__ Og)
{
    const int bh = blockIdx.x;
    const int b = bh >> 5, h = bh & 31;
    const int q0 = blockIdx.y * 64;
    extern __shared__ float sm[];
    float* Qs  = sm;                 // stride 128
    float* Ks  = Qs + 64 * 128;      // stride 132
    float* Vs  = Ks + 64 * 132;      // stride 128
    float* Ps  = Vs + 64 * 128;      // stride 65
    float* m_s = Ps + 64 * 65;
    float* l_s = m_s + 64;
    float* c_s = l_s + 64;

    const int tid = threadIdx.x;
    const int ty = tid >> 4, tx = tid & 15;
    const int rg = tid >> 5, lane = tid & 31;

    for (int idx = tid; idx < 64 * 32; idx += 256) {
        const int r = idx >> 5, d4 = (idx & 31) << 2;
        const int t = b * SQ + q0 + r;
        *(float4*)&Qs[r * 128 + d4] =
            *(const float4*)&Qg[(size_t)t * (3 * D_MODEL) + h * DHEAD + d4];
    }
    if (tid < 64) { m_s[tid] = -1e30f; l_s[tid] = 0.f; }

    float o[8][4];
    #pragma unroll
    for (int i = 0; i < 8; i++)
        { o[i][0]=0.f; o[i][1]=0.f; o[i][2]=0.f; o[i][3]=0.f; }

    const float* Kbh = Kg + (size_t)bh * SKV * DHEAD;
    const float* Vbh = Vg + (size_t)bh * SKV * DHEAD;
    const int ntiles = (HIST + q0) / 64 + 1;
    __syncthreads();

    for (int kt = 0; kt < ntiles; kt++) {
        const int s0 = kt * 64;
        for (int idx = tid; idx < 64 * 32; idx += 256) {
            const int s = idx >> 5, d4 = (idx & 31) << 2;
            *(float4*)&Ks[s * 132 + d4] =
                *(const float4*)&Kbh[(size_t)(s0 + s) * DHEAD + d4];
            *(float4*)&Vs[s * 128 + d4] =
                *(const float4*)&Vbh[(size_t)(s0 + s) * DHEAD + d4];
        }
        __syncthreads();

        float accS[4][4];
        #pragma unroll
        for (int i = 0; i < 4; i++)
            #pragma unroll
            for (int j = 0; j < 4; j++) accS[i][j] = 0.f;

        #pragma unroll 4
        for (int kk = 0; kk < 128; kk += 4) {
            float4 qf[4], kf[4];
            #pragma unroll
            for (int i = 0; i < 4; i++)
                qf[i] = *(float4*)&Qs[(ty * 4 + i) * 128 + kk];
            #pragma unroll
            for (int j = 0; j < 4; j++)
                kf[j] = *(float4*)&Ks[(tx + 16 * j) * 132 + kk];
            #pragma unroll
            for (int i = 0; i < 4; i++)
                #pragma unroll
                for (int j = 0; j < 4; j++) {
                    accS[i][j] += qf[i].x * kf[j].x;
                    accS[i][j] += qf[i].y * kf[j].y;
                    accS[i][j] += qf[i].z * kf[j].z;
                    accS[i][j] += qf[i].w * kf[j].w;
                }
        }

        #pragma unroll
        for (int i = 0; i < 4; i++) {
            const int qpos = HIST + q0 + ty * 4 + i;
            #pragma unroll
            for (int j = 0; j < 4; j++) {
                const int s = s0 + tx + 16 * j;
                float v = accS[i][j] * ATT_SCALE;
                if (s > qpos) v = -1e30f;
                Ps[(ty * 4 + i) * 65 + tx + 16 * j] = v;
            }
        }
        __syncthreads();

        {
            const int row = tid >> 2, qq = tid & 3;
            float* prow = Ps + row * 65 + qq * 16;
            float mx = -1e30f;
            #pragma unroll
            for (int k = 0; k < 16; k++) mx = fmaxf(mx, prow[k]);
            mx = fmaxf(mx, __shfl_xor_sync(0xffffffffu, mx, 1));
            mx = fmaxf(mx, __shfl_xor_sync(0xffffffffu, mx, 2));
            const float m_old = m_s[row];
            const float m_new = fmaxf(m_old, mx);
            float ssum = 0.f;
            #pragma unroll
            for (int k = 0; k < 16; k++) {
                const float p = __expf(prow[k] - m_new);
                prow[k] = p; ssum += p;
            }
            ssum += __shfl_xor_sync(0xffffffffu, ssum, 1);
            ssum += __shfl_xor_sync(0xffffffffu, ssum, 2);
            if (qq == 0) {
                const float corr = __expf(m_old - m_new);
                l_s[row] = l_s[row] * corr + ssum;
                m_s[row] = m_new;
                c_s[row] = corr;
            }
        }
        __syncthreads();

        #pragma unroll
        for (int i = 0; i < 8; i++) {
            const float c = c_s[rg * 8 + i];
            o[i][0] *= c; o[i][1] *= c; o[i][2] *= c; o[i][3] *= c;
        }
        #pragma unroll 4
        for (int kv = 0; kv < 64; kv++) {
            const float4 v = *(float4*)&Vs[kv * 128 + lane * 4];
            #pragma unroll
            for (int i = 0; i < 8; i++) {
                const float p = Ps[(rg * 8 + i) * 65 + kv];
                o[i][0] += p * v.x; o[i][1] += p * v.y;
                o[i][2] += p * v.z; o[i][3] += p * v.w;
            }
        }
        __syncthreads();
    }

    #pragma unroll
    for (int i = 0; i < 8; i++) {
        const int r = rg * 8 + i;
        const float inv = 1.f / l_s[r];
        const int t = b * SQ + q0 + r;
        float4 res;
        res.x = o[i][0] * inv; res.y = o[i][1] * inv;
        res.z = o[i][2] * inv; res.w = o[i][3] * inv;
        *(float4*)&Og[(size_t)t * D_MODEL + h * DHEAD + lane * 4] = res;
    }
}

// =====================================================================
// launch
// =====================================================================
extern "C" void kernel_launch(void* const* d_in, const int* in_sizes, int n_in,
                              void* d_out, int out_size)
{
    const float* hidden  = (const float*)d_in[0];
    const float* w_qkv   = (const float*)d_in[1];
    const float* b_qkv   = (const float*)d_in[2];
    const float* w_proj  = (const float*)d_in[3];
    const float* cosT    = (const float*)d_in[4];
    const float* sinT    = (const float*)d_in[5];
    const float* kcache  = (const float*)d_in[6];
    const float* vcache  = (const float*)d_in[7];
    const int*   blkOff  = (const int*)d_in[8];
    float* out = (float*)d_out;

    float *qkv_p, *k_p, *v_p, *attn_p;
    cudaGetSymbolAddress((void**)&qkv_p,  g_qkv);
    cudaGetSymbolAddress((void**)&k_p,    g_k);
    cudaGetSymbolAddress((void**)&v_p,    g_v);
    cudaGetSymbolAddress((void**)&attn_p, g_attn);

    cudaFuncSetAttribute(flash_kernel,
                         cudaFuncAttributeMaxDynamicSharedMemorySize,
                         FL_SMEM_BYTES);

    // 1) QKV projection: [T, 3D] = hidden[T,D] @ w_qkv[D,3D] + b
    tf32_gemm_kernel<<<dim3(3 * D_MODEL / 128, T_TOK / 128), 256>>>(
        hidden, w_qkv, b_qkv, qkv_p, T_TOK, 3 * D_MODEL, D_MODEL);

    // 2) RoPE + logn on Q (in place)
    rope_q_kernel<<<dim3(T_TOK, H_HEADS), 64>>>(qkv_p, cosT, sinT);

    // 3) build contiguous K/V (cache gather + RoPE on new K)
    build_kv_kernel<<<dim3(SKV, B_SEQ), 128>>>(
        qkv_p, kcache, vcache, blkOff, cosT, sinT, k_p, v_p);

    // 4) causal flash attention
    flash_kernel<<<dim3(B_SEQ * H_HEADS, SQ / 64), 256, FL_SMEM_BYTES>>>(
        qkv_p, k_p, v_p, attn_p);

    // 5) output projection: out[T,D] = attn[T,D] @ w_proj[D,D]
    tf32_gemm_kernel<<<dim3(D_MODEL / 128, T_TOK / 128), 256>>>(
        attn_p, w_proj, nullptr, out, T_TOK, D_MODEL, D_MODEL);
}